// round 2
// baseline (speedup 1.0000x reference)
#include <cuda_runtime.h>
#include <cuda_bf16.h>

// HistByProfMultiChannel: x (16,128,56,56) f32, hist_edges (128,10) f32
// out (16,128,11) f32.
// For each (bt,c): 10 gaussian-bin sums over the 56*56 plane + 1 sigmoid-tail sum.

#define NE        10          // number of edges (= gaussian bins)
#define NBINS     (NE + 1)
#define HW        3136        // 56*56
#define HW4       (HW / 4)    // 784 float4 per (bt,c) plane
#define THREADS   256
#define NWARPS    (THREADS / 32)

__device__ __forceinline__ float ex2f_fast(float x) {
    float r;
    asm("ex2.approx.ftz.f32 %0, %1;" : "=f"(r) : "f"(x));
    return r;
}
__device__ __forceinline__ float rcpf_fast(float x) {
    float r;
    asm("rcp.approx.ftz.f32 %0, %1;" : "=f"(r) : "f"(x));
    return r;
}

__global__ __launch_bounds__(THREADS)
void hist_by_prof_kernel(const float4* __restrict__ x4,
                         const float*  __restrict__ edges,
                         float*        __restrict__ out,
                         int C) {
    const int pair = blockIdx.x;          // bt * C + c
    const int ch   = pair % C;

    // ---- Load this channel's edges (uniform across block, L1 broadcast) ----
    float ev[NE];
#pragma unroll
    for (int i = 0; i < NE; i++) ev[i] = __ldg(edges + ch * NE + i);

    // ---- Precompute per-bin quadratic coefficients ----
    // gauss_k(x) = exp(-0.5*((x-mu)/sig)^2) = exp2( A*x^2 + B*x + Cc )
    // with A = -0.5*log2(e)/sig^2, B = -2*A*mu, Cc = A*mu^2
    const float LOG2E = 1.4426950408889634f;
    float ca[NE], cb[NE], cc[NE];
#pragma unroll
    for (int k = 0; k < NE; k++) {
        float mu, sig;
        if (k == 0) {
            mu  = ev[0];
            sig = (ev[0] - ev[1]) * (1.0f / 3.0f) + 1e-6f;
        } else {
            mu  = 0.5f * (ev[k - 1] + ev[k]);
            sig = (ev[k - 1] - ev[k]) * (1.0f / 3.0f) + 1e-6f;
        }
        float inv = 1.0f / sig;
        float A   = -0.5f * LOG2E * inv * inv;
        ca[k] = A;
        cb[k] = -2.0f * A * mu;
        cc[k] = A * mu * mu;
    }
    // sigmoid tail: 1/(1+exp(-20*(x-e9))) = 1/(1+exp2(sb*x + sc))
    const float sb = -20.0f * LOG2E;
    const float sc =  20.0f * LOG2E * ev[NE - 1];

    // ---- Accumulate over pixels ----
    float acc[NBINS];
#pragma unroll
    for (int k = 0; k < NBINS; k++) acc[k] = 0.0f;

    const float4* xp = x4 + (long long)pair * HW4;
    for (int j = threadIdx.x; j < HW4; j += THREADS) {
        float4 v = __ldg(xp + j);
        float xs[4] = {v.x, v.y, v.z, v.w};
#pragma unroll
        for (int p = 0; p < 4; p++) {
            float xv = xs[p];
#pragma unroll
            for (int k = 0; k < NE; k++) {
                float arg = fmaf(fmaf(ca[k], xv, cb[k]), xv, cc[k]);
                acc[k] += ex2f_fast(arg);
            }
            float t = ex2f_fast(fmaf(sb, xv, sc));
            acc[NE] += rcpf_fast(1.0f + t);
        }
    }

    // ---- Reduction: warp shuffle, then cross-warp via smem ----
    const unsigned m = 0xffffffffu;
#pragma unroll
    for (int k = 0; k < NBINS; k++) {
        float v = acc[k];
        v += __shfl_down_sync(m, v, 16);
        v += __shfl_down_sync(m, v, 8);
        v += __shfl_down_sync(m, v, 4);
        v += __shfl_down_sync(m, v, 2);
        v += __shfl_down_sync(m, v, 1);
        acc[k] = v;
    }

    __shared__ float sred[NWARPS][NBINS];
    const int warp = threadIdx.x >> 5;
    const int lane = threadIdx.x & 31;
    if (lane == 0) {
#pragma unroll
        for (int k = 0; k < NBINS; k++) sred[warp][k] = acc[k];
    }
    __syncthreads();

    if (threadIdx.x < NBINS) {
        float s = 0.0f;
#pragma unroll
        for (int w = 0; w < NWARPS; w++) s += sred[w][threadIdx.x];
        out[(long long)pair * NBINS + threadIdx.x] = s;
    }
}

extern "C" void kernel_launch(void* const* d_in, const int* in_sizes, int n_in,
                              void* d_out, int out_size) {
    const float4* x4    = (const float4*)d_in[0];   // (16,128,56,56) f32
    const float*  edges = (const float*) d_in[1];   // (128,10) f32
    float*        out   = (float*)d_out;            // (16,128,11) f32

    const int C     = in_sizes[1] / NE;             // 128
    const int pairs = out_size / NBINS;             // 16*128 = 2048

    hist_by_prof_kernel<<<pairs, THREADS>>>(x4, edges, out, C);
}